// round 4
// baseline (speedup 1.0000x reference)
#include <cuda_runtime.h>
#include <cstdint>
#include <cstddef>
#include <math.h>

#define B_  32
#define T_  512
#define H_  512
#define G4_ 2048   // 4*H
#define C_  32
#define CH_ 128    // k-chunk for scan pipeline

// ---------------- scratch (device globals; zero-init, no allocation) ----------------
__device__ float g_embout[(size_t)T_ * 512 * B_];        // [T][E=512][B]
__device__ float g_xwf[(size_t)T_ * G4_ * B_];           // [T][4H][B]
__device__ float g_xwb[(size_t)T_ * G4_ * B_];
__device__ float g_l1in[(size_t)T_ * 1024 * B_];         // [T][2H][B]
__device__ float g_l2out[(size_t)T_ * 1024 * B_];
__device__ float g_hstate[2][2][H_ * B_];                // [dir][pingpong][u*32+b]
__device__ unsigned g_bar[2];

// ---------------- packed f32x2 helpers ----------------
__device__ __forceinline__ unsigned long long pk2(float lo, float hi) {
    unsigned long long r;
    asm("mov.b64 %0, {%1, %2};" : "=l"(r)
        : "r"(__float_as_uint(lo)), "r"(__float_as_uint(hi)));
    return r;
}
__device__ __forceinline__ void upk2(float& lo, float& hi, unsigned long long v) {
    unsigned a, b;
    asm("mov.b64 {%0, %1}, %2;" : "=r"(a), "=r"(b) : "l"(v));
    lo = __uint_as_float(a); hi = __uint_as_float(b);
}
__device__ __forceinline__ void fma2(unsigned long long& d, unsigned long long a,
                                     unsigned long long b) {
    asm("fma.rn.f32x2 %0, %1, %2, %3;" : "=l"(d) : "l"(a), "l"(b), "l"(d));
}

// cp.async.cg (L2-only: h is produced by other SMs, must bypass L1)
__device__ __forceinline__ void cp16(void* dst_smem, const void* src_gmem) {
    unsigned u = (unsigned)__cvta_generic_to_shared(dst_smem);
    asm volatile("cp.async.cg.shared.global [%0], [%1], 16;"
                 :: "r"(u), "l"(src_gmem) : "memory");
}
__device__ __forceinline__ void cp_commit() {
    asm volatile("cp.async.commit_group;" ::: "memory");
}
template <int N> __device__ __forceinline__ void cp_wait() {
    asm volatile("cp.async.wait_group %0;" :: "n"(N) : "memory");
}

__device__ __forceinline__ float sigm(float x)  { return 1.f / (1.f + __expf(-x)); }
__device__ __forceinline__ float tanhp(float x) { return 2.f / (1.f + __expf(-2.f * x)) - 1.f; }

// ---------------- reset barrier + h state ----------------
__global__ void reset_k() {
    int tid = blockIdx.x * blockDim.x + threadIdx.x;
    if (tid < 2) g_bar[tid] = 0u;
    float* hs = &g_hstate[0][0][0];
    for (int i = tid; i < 2 * 2 * H_ * B_; i += blockDim.x * gridDim.x) hs[i] = 0.f;
}

// ---------------- embedding: out[tt][e][b] = emb[x[b][tt]][e] ----------------
__global__ __launch_bounds__(256) void embed_k(
    const int* __restrict__ x, const float* __restrict__ emb, float* __restrict__ out)
{
    __shared__ float s[16 * 513];
    const int tt = blockIdx.x, tid = threadIdx.x;
    for (int half = 0; half < 2; half++) {
        for (int bb = 0; bb < 16; bb++) {
            int row = x[(half * 16 + bb) * T_ + tt];
            const float* er = emb + (size_t)row * 512;
            for (int e = tid; e < 512; e += 256) s[bb * 513 + e] = __ldg(er + e);
        }
        __syncthreads();
        for (int li = tid; li < 16 * 512; li += 256) {
            int e = li >> 4, bb = li & 15;
            out[(size_t)tt * (512 * B_) + e * 32 + half * 16 + bb] = s[bb * 513 + e];
        }
        __syncthreads();
    }
}

// ---------------- input GEMM: out[tt][n][b] = sum_k A[tt][k][b]*W[n][k] + bih[n]+bhh[n]
// M = T*32 (m = tt*32+b), N = 2048, K = 512 or 1024.  BM=128 BN=64 BK=16, 256 thr.
// B tile stored PRE-DUPLICATED ((w,w) 64-bit) so the inner loop has no packing movs:
// 3x LDS.128 + 16x fma.rn.f32x2 per k.
__global__ __launch_bounds__(256) void gemm_xw(
    const float* __restrict__ A, const float* __restrict__ W,
    const float* __restrict__ bih, const float* __restrict__ bhh,
    float* __restrict__ out, int K)
{
    __shared__ float As[16 * 128];
    __shared__ unsigned long long Bsd[16 * 66];   // [k][n] dup pairs, stride 66
    const int tid = threadIdx.x;
    const int n0 = blockIdx.x << 6;
    const int m0 = blockIdx.y << 7;
    const int tt0 = m0 >> 5;
    const int tm4 = (tid & 15) << 2;
    const int tn4 = (tid >> 4) << 2;
    unsigned long long acc[4][4];
#pragma unroll
    for (int i = 0; i < 4; i++)
#pragma unroll
        for (int j = 0; j < 4; j++) acc[i][j] = 0ULL;

    for (int k0 = 0; k0 < K; k0 += 16) {
#pragma unroll
        for (int i = 0; i < 8; i++) {
            int li = tid + (i << 8);
            int ltt = li >> 9, k = (li >> 5) & 15, bb = li & 31;
            As[k * 128 + ltt * 32 + bb] =
                A[(size_t)(tt0 + ltt) * K * 32 + (size_t)(k0 + k) * 32 + bb];
        }
#pragma unroll
        for (int i = 0; i < 4; i++) {
            int li = tid + (i << 8);
            int n = li >> 4, k = li & 15;
            float w = W[(size_t)(n0 + n) * K + k0 + k];
            Bsd[k * 66 + n] = pk2(w, w);
        }
        __syncthreads();
#pragma unroll
        for (int kk = 0; kk < 16; kk++) {
            ulonglong2 b01 = *(const ulonglong2*)&Bsd[kk * 66 + tn4];
            ulonglong2 b23 = *(const ulonglong2*)&Bsd[kk * 66 + tn4 + 2];
            ulonglong2 a0 = *(const ulonglong2*)&As[kk * 128 + tm4];
            ulonglong2 a1 = *(const ulonglong2*)&As[kk * 128 + tm4 + 64];
            fma2(acc[0][0], a0.x, b01.x); fma2(acc[0][1], a0.x, b01.y);
            fma2(acc[0][2], a0.x, b23.x); fma2(acc[0][3], a0.x, b23.y);
            fma2(acc[1][0], a0.y, b01.x); fma2(acc[1][1], a0.y, b01.y);
            fma2(acc[1][2], a0.y, b23.x); fma2(acc[1][3], a0.y, b23.y);
            fma2(acc[2][0], a1.x, b01.x); fma2(acc[2][1], a1.x, b01.y);
            fma2(acc[2][2], a1.x, b23.x); fma2(acc[2][3], a1.x, b23.y);
            fma2(acc[3][0], a1.y, b01.x); fma2(acc[3][1], a1.y, b01.y);
            fma2(acc[3][2], a1.y, b23.x); fma2(acc[3][3], a1.y, b23.y);
        }
        __syncthreads();
    }
    const int mb[4] = {tm4, tm4 + 2, tm4 + 64, tm4 + 66};
#pragma unroll
    for (int j = 0; j < 4; j++) {
        int n = n0 + tn4 + j;
        float bias = __ldg(bih + n) + __ldg(bhh + n);
#pragma unroll
        for (int p = 0; p < 4; p++) {
            float lo, hi;
            upk2(lo, hi, acc[p][j]);
            int mm = m0 + mb[p];
            *(float2*)&out[(size_t)(mm >> 5) * (G4_ * B_) + (size_t)n * 32 + (mm & 31)] =
                make_float2(lo + bias, hi + bias);
        }
    }
}

// ---------------- persistent bidirectional LSTM scan ----------------
// 128 CTAs: 0..63 fwd, 64..127 bwd. CTA owns 8 units; 256 threads:
// thread = (uu 0..7, gp 0..1, bp 0..15): gate-pair {i,f} or {g,o} x batch-pair.
// Weights pre-DUPLICATED in SMEM as (wA,wA,wB,wB) so the inner loop is
// LDS.64(h pair, already packed) + LDS.128(w) + 2x fma.rn.f32x2 — zero mov packing.
// Gate regroup at step end via 2 warp shuffles. h broadcast via cp.async.cg
// double-buffered 4-chunk pipeline. c state in registers.
__global__ __launch_bounds__(256, 1) void lstm_scan(
    const float* __restrict__ xw_f, const float* __restrict__ xw_b,
    const float* __restrict__ Whh_f, const float* __restrict__ Whh_b,
    float* __restrict__ outbuf)
{
    extern __shared__ float smem[];
    float* sWd = smem;                     // [512][8][2] float4 dup: 131072 B
    float* sh0 = smem + 512 * 64;          // [CH_][32]
    float* sh1 = sh0 + CH_ * 32;
    const int tid = threadIdx.x;
    const int dir = blockIdx.x >> 6;
    const int u0  = (blockIdx.x & 63) << 3;
    const float* xw  = dir ? xw_b : xw_f;
    const float* Whh = dir ? Whh_b : Whh_f;
    unsigned* bar = &g_bar[dir];

    // one-time: duplicated-pair weight slice. sWd float4 index = k*16 + uu*2 + gp,
    // value = (w_gate(2gp), dup, w_gate(2gp+1), dup) for unit u0+uu at column k.
    for (int li = tid; li < 8192; li += 256) {
        int k   = li >> 4;
        int uu2 = (li >> 1) & 7;
        int gp2 = li & 1;
        int rowA = (gp2 * 2) * 512 + u0 + uu2;
        float wA = Whh[(size_t)rowA * 512 + k];
        float wB = Whh[(size_t)(rowA + 512) * 512 + k];
        ((float4*)sWd)[li] = make_float4(wA, wA, wB, wB);
    }
    __syncthreads();

    const int bp = tid & 15;          // batches 2bp, 2bp+1
    const int gp = (tid >> 4) & 1;    // gate pair: 0 -> {i,f}, 1 -> {g,o}
    const int uu = tid >> 5;          // 0..7
    const int b  = (bp << 1) + gp;    // batch this thread finalizes
    float c_reg = 0.f;
    unsigned target = 0;

    for (int step = 0; step < 512; step++) {
        const int t = dir ? (511 - step) : step;
        const float* hsrc = g_hstate[dir][step & 1];

        // xw gate loads for this step issued early: latency hides under GEMM
        const float* xb = xw + (size_t)t * 65536 + (size_t)(u0 + uu) * 32 + b;
        float xi = __ldg(xb);
        float xf = __ldg(xb + 16384);
        float xg = __ldg(xb + 32768);
        float xo = __ldg(xb + 49152);

        // prologue: prefetch h chunk 0
        {
            const float4* src = (const float4*)hsrc;
            float4* dst = (float4*)sh0;
#pragma unroll
            for (int i = 0; i < 4; i++) cp16(dst + tid + (i << 8), src + tid + (i << 8));
            cp_commit();
        }

        unsigned long long accA = 0, accB = 0;
#pragma unroll
        for (int ch = 0; ch < 4; ch++) {
            if (ch < 3) {
                const float4* src = (const float4*)hsrc + ((ch + 1) << 10);
                float4* dst = (float4*)(((ch + 1) & 1) ? sh1 : sh0);
#pragma unroll
                for (int i = 0; i < 4; i++) cp16(dst + tid + (i << 8), src + tid + (i << 8));
                cp_commit();
                cp_wait<1>();
            } else {
                cp_wait<0>();
            }
            __syncthreads();
            const float* buf = (ch & 1) ? sh1 : sh0;
            const unsigned long long* hb = (const unsigned long long*)buf + bp;
            const ulonglong2* wp = (const ulonglong2*)sWd + ((ch * CH_) << 4) + (uu << 1) + gp;
#pragma unroll 8
            for (int kk = 0; kk < CH_; kk++) {
                unsigned long long h2 = hb[kk << 4];
                ulonglong2 w = wp[(size_t)kk << 4];
                fma2(accA, h2, w.x);
                fma2(accB, h2, w.y);
            }
            __syncthreads();
        }

        // regroup gates: thread gp=0 holds (i,f) pairs, gp=1 holds (g,o) pairs.
        float A_lo, A_hi, B_lo, B_hi;
        upk2(A_lo, A_hi, accA);
        upk2(B_lo, B_hi, accB);
        float sendA = gp ? A_lo : A_hi;
        float sendB = gp ? B_lo : B_hi;
        float recvA = __shfl_xor_sync(0xffffffffu, sendA, 16);
        float recvB = __shfl_xor_sync(0xffffffffu, sendB, 16);
        float pi = (gp ? recvA : A_lo) + xi;
        float pf = (gp ? recvB : B_lo) + xf;
        float pg = (gp ? A_hi : recvA) + xg;
        float po = (gp ? B_hi : recvB) + xo;

        float ig = sigm(pi), fg = sigm(pf), gg = tanhp(pg), og = sigm(po);
        c_reg = fg * c_reg + ig * gg;
        float hv = og * tanhp(c_reg);

        int hidx = (u0 + uu) * 32 + b;
        __stcg(&g_hstate[dir][(step + 1) & 1][hidx], hv);
        outbuf[(size_t)t * 32768 + (size_t)((dir << 9) + u0 + uu) * 32 + b] = hv;

        __threadfence();
        __syncthreads();
        if (tid == 0) atomicAdd(bar, 1u);
        target += 64;
        if (tid == 0) {
            while (*((volatile unsigned*)bar) < target) {}
            __threadfence();
        }
        __syncthreads();
    }
}

// ---------------- classifier + log_softmax, out[b][c][tt] ----------------
__global__ __launch_bounds__(256) void classifier_k(
    const float* __restrict__ h, const float* __restrict__ Wc,
    const float* __restrict__ bc, const float* __restrict__ truth,
    const int* __restrict__ tf, float* __restrict__ out)
{
    __shared__ float sL[32][33];
    const int tt = blockIdx.x, tid = threadIdx.x;
    const int b = tid & 31, cg = tid >> 5;
    float acc0 = 0.f, acc1 = 0.f, acc2 = 0.f, acc3 = 0.f;
    const float* hp = h + (size_t)tt * (1024 * B_) + b;
    const float* w0 = Wc + (size_t)(cg * 4 + 0) * 1025 + 1;
    const float* w1 = Wc + (size_t)(cg * 4 + 1) * 1025 + 1;
    const float* w2 = Wc + (size_t)(cg * 4 + 2) * 1025 + 1;
    const float* w3 = Wc + (size_t)(cg * 4 + 3) * 1025 + 1;
#pragma unroll 4
    for (int k = 0; k < 1024; k++) {
        float hv = __ldg(hp + (size_t)k * 32);
        acc0 += hv * __ldg(w0 + k);
        acc1 += hv * __ldg(w1 + k);
        acc2 += hv * __ldg(w2 + k);
        acc3 += hv * __ldg(w3 + k);
    }
    float past = 0.f;
    if (tf[0] != 0 && tt > 0) past = truth[(size_t)b * T_ + tt - 1];
    {
        float a[4] = {acc0, acc1, acc2, acc3};
#pragma unroll
        for (int j = 0; j < 4; j++) {
            int c = cg * 4 + j;
            sL[b][c] = a[j] + __ldg(bc + c) + past * __ldg(Wc + (size_t)c * 1025);
        }
    }
    __syncthreads();
    int w = tid >> 5, lane = tid & 31;
    for (int rep = 0; rep < 4; rep++) {
        int bb = w + (rep << 3);
        float v = sL[bb][lane];
        float m = v;
#pragma unroll
        for (int o = 16; o > 0; o >>= 1) m = fmaxf(m, __shfl_xor_sync(0xffffffffu, m, o));
        float e = expf(v - m);
        float s = e;
#pragma unroll
        for (int o = 16; o > 0; o >>= 1) s += __shfl_xor_sync(0xffffffffu, s, o);
        out[((size_t)bb * 32 + lane) * T_ + tt] = v - m - logf(s);
    }
}

// ---------------- launch ----------------
extern "C" void kernel_launch(void* const* d_in, const int* in_sizes, int n_in,
                              void* d_out, int out_size)
{
    (void)in_sizes; (void)n_in; (void)out_size;
    const int*   x     = (const int*)d_in[0];
    const float* truth = (const float*)d_in[1];
    const int*   tf    = (const int*)d_in[2];
    const float* emb   = (const float*)d_in[3];
    const float* Wih0f = (const float*)d_in[4];
    const float* Whh0f = (const float*)d_in[5];
    const float* bih0f = (const float*)d_in[6];
    const float* bhh0f = (const float*)d_in[7];
    const float* Wih0b = (const float*)d_in[8];
    const float* Whh0b = (const float*)d_in[9];
    const float* bih0b = (const float*)d_in[10];
    const float* bhh0b = (const float*)d_in[11];
    const float* Wih1f = (const float*)d_in[12];
    const float* Whh1f = (const float*)d_in[13];
    const float* bih1f = (const float*)d_in[14];
    const float* bhh1f = (const float*)d_in[15];
    const float* Wih1b = (const float*)d_in[16];
    const float* Whh1b = (const float*)d_in[17];
    const float* bih1b = (const float*)d_in[18];
    const float* bhh1b = (const float*)d_in[19];
    const float* Wc    = (const float*)d_in[20];
    const float* bc    = (const float*)d_in[21];
    float* out = (float*)d_out;

    void *p_embout, *p_xwf, *p_xwb, *p_l1in, *p_l2out;
    cudaGetSymbolAddress(&p_embout, g_embout);
    cudaGetSymbolAddress(&p_xwf, g_xwf);
    cudaGetSymbolAddress(&p_xwb, g_xwb);
    cudaGetSymbolAddress(&p_l1in, g_l1in);
    cudaGetSymbolAddress(&p_l2out, g_l2out);

    const int scan_smem = (512 * 64 + 2 * CH_ * 32) * 4;   // 131072 + 32768 = 163840 B
    cudaFuncSetAttribute(lstm_scan, cudaFuncAttributeMaxDynamicSharedMemorySize, scan_smem);

    dim3 ggrid(32, 128);  // N/64, M/128

    embed_k<<<T_, 256>>>(x, emb, (float*)p_embout);
    reset_k<<<64, 256>>>();
    gemm_xw<<<ggrid, 256>>>((const float*)p_embout, Wih0f, bih0f, bhh0f, (float*)p_xwf, 512);
    gemm_xw<<<ggrid, 256>>>((const float*)p_embout, Wih0b, bih0b, bhh0b, (float*)p_xwb, 512);
    lstm_scan<<<128, 256, scan_smem>>>((const float*)p_xwf, (const float*)p_xwb,
                                       Whh0f, Whh0b, (float*)p_l1in);
    reset_k<<<64, 256>>>();
    gemm_xw<<<ggrid, 256>>>((const float*)p_l1in, Wih1f, bih1f, bhh1f, (float*)p_xwf, 1024);
    gemm_xw<<<ggrid, 256>>>((const float*)p_l1in, Wih1b, bih1b, bhh1b, (float*)p_xwb, 1024);
    lstm_scan<<<128, 256, scan_smem>>>((const float*)p_xwf, (const float*)p_xwb,
                                       Whh1f, Whh1b, (float*)p_l2out);
    classifier_k<<<T_, 256>>>((const float*)p_l2out, Wc, bc, truth, tf, out);
}

// round 8
// speedup vs baseline: 1.3553x; 1.3553x over previous
#include <cuda_runtime.h>
#include <cstdint>
#include <cstddef>
#include <math.h>

#define B_  32
#define T_  512
#define H_  512
#define G4_ 2048   // 4*H
#define C_  32
#define CH_ 128    // k-chunk for scan pipeline

// ---------------- scratch (device globals; zero-init, no allocation) ----------------
__device__ float g_embout[(size_t)T_ * 512 * B_];        // [T][E=512][B]
__device__ float g_xwf[(size_t)T_ * G4_ * B_];           // [T][4H][B]
__device__ float g_xwb[(size_t)T_ * G4_ * B_];
__device__ float g_l1in[(size_t)T_ * 1024 * B_];         // [T][2H][B]
__device__ float g_l2out[(size_t)T_ * 1024 * B_];
__device__ float g_hstate[2][2][H_ * B_];                // [dir][pingpong][u*32+b]
__device__ unsigned g_bar[2];

// ---------------- packed f32x2 helpers ----------------
__device__ __forceinline__ unsigned long long pk2(float lo, float hi) {
    unsigned long long r;
    asm("mov.b64 %0, {%1, %2};" : "=l"(r)
        : "r"(__float_as_uint(lo)), "r"(__float_as_uint(hi)));
    return r;
}
__device__ __forceinline__ void upk2(float& lo, float& hi, unsigned long long v) {
    unsigned a, b;
    asm("mov.b64 {%0, %1}, %2;" : "=r"(a), "=r"(b) : "l"(v));
    lo = __uint_as_float(a); hi = __uint_as_float(b);
}
__device__ __forceinline__ void fma2(unsigned long long& d, unsigned long long a,
                                     unsigned long long b) {
    asm("fma.rn.f32x2 %0, %1, %2, %3;" : "=l"(d) : "l"(a), "l"(b), "l"(d));
}

// cp.async.cg (L2-only: h is produced by other SMs, must bypass L1)
__device__ __forceinline__ void cp16(void* dst_smem, const void* src_gmem) {
    unsigned u = (unsigned)__cvta_generic_to_shared(dst_smem);
    asm volatile("cp.async.cg.shared.global [%0], [%1], 16;"
                 :: "r"(u), "l"(src_gmem) : "memory");
}
__device__ __forceinline__ void cp_commit() {
    asm volatile("cp.async.commit_group;" ::: "memory");
}
template <int N> __device__ __forceinline__ void cp_wait() {
    asm volatile("cp.async.wait_group %0;" :: "n"(N) : "memory");
}

__device__ __forceinline__ float sigm(float x)  { return 1.f / (1.f + __expf(-x)); }
__device__ __forceinline__ float tanhp(float x) { return 2.f / (1.f + __expf(-2.f * x)) - 1.f; }

// ---------------- reset barrier + h state ----------------
__global__ void reset_k() {
    int tid = blockIdx.x * blockDim.x + threadIdx.x;
    if (tid < 2) g_bar[tid] = 0u;
    float* hs = &g_hstate[0][0][0];
    for (int i = tid; i < 2 * 2 * H_ * B_; i += blockDim.x * gridDim.x) hs[i] = 0.f;
}

// ---------------- embedding: out[tt][e][b] = emb[x[b][tt]][e] ----------------
__global__ __launch_bounds__(256) void embed_k(
    const int* __restrict__ x, const float* __restrict__ emb, float* __restrict__ out)
{
    __shared__ float s[16 * 513];
    const int tt = blockIdx.x, tid = threadIdx.x;
    for (int half = 0; half < 2; half++) {
        for (int bb = 0; bb < 16; bb++) {
            int row = x[(half * 16 + bb) * T_ + tt];
            const float* er = emb + (size_t)row * 512;
            for (int e = tid; e < 512; e += 256) s[bb * 513 + e] = __ldg(er + e);
        }
        __syncthreads();
        for (int li = tid; li < 16 * 512; li += 256) {
            int e = li >> 4, bb = li & 15;
            out[(size_t)tt * (512 * B_) + e * 32 + half * 16 + bb] = s[bb * 513 + e];
        }
        __syncthreads();
    }
}

// ---------------- input GEMM: out[tt][n][b] = sum_k A[tt][k][b]*W[n][k] + bih[n]+bhh[n]
// M = T*32 (m = tt*32+b), N = 2048, K = 512 or 1024.  BM=128 BN=64 BK=16, 256 thr.
// (round-1 version, measured 754us @ K=512, fma 57.3%)
__global__ __launch_bounds__(256) void gemm_xw(
    const float* __restrict__ A, const float* __restrict__ W,
    const float* __restrict__ bih, const float* __restrict__ bhh,
    float* __restrict__ out, int K)
{
    __shared__ float As[16 * 128];
    __shared__ float Bs[16 * 68];
    const int tid = threadIdx.x;
    const int n0 = blockIdx.x << 6;
    const int m0 = blockIdx.y << 7;
    const int tt0 = m0 >> 5;
    const int tm4 = (tid & 15) << 2;
    const int tn4 = (tid >> 4) << 2;
    unsigned long long acc[4][4];
#pragma unroll
    for (int i = 0; i < 4; i++)
#pragma unroll
        for (int j = 0; j < 4; j++) acc[i][j] = 0ULL;

    for (int k0 = 0; k0 < K; k0 += 16) {
#pragma unroll
        for (int i = 0; i < 8; i++) {
            int li = tid + (i << 8);
            int ltt = li >> 9, k = (li >> 5) & 15, bb = li & 31;
            As[k * 128 + ltt * 32 + bb] =
                A[(size_t)(tt0 + ltt) * K * 32 + (size_t)(k0 + k) * 32 + bb];
        }
#pragma unroll
        for (int i = 0; i < 4; i++) {
            int li = tid + (i << 8);
            int n = li >> 4, k = li & 15;
            Bs[k * 68 + n] = W[(size_t)(n0 + n) * K + k0 + k];
        }
        __syncthreads();
#pragma unroll
        for (int kk = 0; kk < 16; kk++) {
            float4 bv = *(const float4*)&Bs[kk * 68 + tn4];
            ulonglong2 a0 = *(const ulonglong2*)&As[kk * 128 + tm4];
            ulonglong2 a1 = *(const ulonglong2*)&As[kk * 128 + tm4 + 64];
            unsigned long long b0 = pk2(bv.x, bv.x);
            unsigned long long b1 = pk2(bv.y, bv.y);
            unsigned long long b2 = pk2(bv.z, bv.z);
            unsigned long long b3 = pk2(bv.w, bv.w);
            fma2(acc[0][0], a0.x, b0); fma2(acc[0][1], a0.x, b1);
            fma2(acc[0][2], a0.x, b2); fma2(acc[0][3], a0.x, b3);
            fma2(acc[1][0], a0.y, b0); fma2(acc[1][1], a0.y, b1);
            fma2(acc[1][2], a0.y, b2); fma2(acc[1][3], a0.y, b3);
            fma2(acc[2][0], a1.x, b0); fma2(acc[2][1], a1.x, b1);
            fma2(acc[2][2], a1.x, b2); fma2(acc[2][3], a1.x, b3);
            fma2(acc[3][0], a1.y, b0); fma2(acc[3][1], a1.y, b1);
            fma2(acc[3][2], a1.y, b2); fma2(acc[3][3], a1.y, b3);
        }
        __syncthreads();
    }
    const int mb[4] = {tm4, tm4 + 2, tm4 + 64, tm4 + 66};
#pragma unroll
    for (int j = 0; j < 4; j++) {
        int n = n0 + tn4 + j;
        float bias = __ldg(bih + n) + __ldg(bhh + n);
#pragma unroll
        for (int p = 0; p < 4; p++) {
            float lo, hi;
            upk2(lo, hi, acc[p][j]);
            int mm = m0 + mb[p];
            *(float2*)&out[(size_t)(mm >> 5) * (G4_ * B_) + (size_t)n * 32 + (mm & 31)] =
                make_float2(lo + bias, hi + bias);
        }
    }
}

// ---------------- persistent bidirectional LSTM scan ----------------
// 128 CTAs: 0..63 fwd, 64..127 bwd. CTA owns 8 units; 128 threads:
// thread = (uu 0..7, bp 0..15) computes 4 gates x 2 batches (round-1 measured core).
// Tail changes vs round-1: single release fence (acquire side dropped — data
// path is L2-only via cp.async.cg / st.cg), outbuf store + next-step xw prefetch
// moved after the fence to hide DRAM latency under the barrier spin, a
// TRIPLE-buffered h pipeline with ONE __syncthreads per chunk, and nanosleep
// backoff in the barrier spin to cut LTS pressure on the barrier line.
__global__ __launch_bounds__(128, 1) void lstm_scan(
    const float* __restrict__ xw_f, const float* __restrict__ xw_b,
    const float* __restrict__ Whh_f, const float* __restrict__ Whh_b,
    float* __restrict__ outbuf)
{
    extern __shared__ float smem[];
    float* sW  = smem;                    // [512][32] : sW[k*32 + uu*4 + g]
    float* sh0 = smem + 512 * 32;         // 3 x [CH_][32]
    float* sh1 = sh0 + CH_ * 32;
    float* sh2 = sh1 + CH_ * 32;
    const int tid = threadIdx.x;
    const int dir = blockIdx.x >> 6;
    const int u0  = (blockIdx.x & 63) << 3;
    const float* xw  = dir ? xw_b : xw_f;
    const float* Whh = dir ? Whh_b : Whh_f;
    unsigned* bar = &g_bar[dir];

    // one-time: transposed Whh slice, unit-major float4 per (k, unit)
    for (int li = tid; li < 32 * 512; li += 128) {
        int r = li >> 9;          // uu*4+g
        int k = li & 511;
        int uu2 = r >> 2, g = r & 3;
        sW[k * 32 + r] = Whh[((size_t)((g << 9) + u0 + uu2)) * 512 + k];
    }
    __syncthreads();

    const int bp = tid & 15;   // batches 2bp, 2bp+1
    const int uu = tid >> 4;   // 0..7
    float c0 = 0.f, c1 = 0.f;
    unsigned target = 0;

    // preload xw for step 0
    const float* xb0 = xw + (size_t)(dir ? 511 : 0) * 65536 + (size_t)(u0 + uu) * 32 + (bp << 1);
    float2 xi = __ldg((const float2*)(xb0));
    float2 xf = __ldg((const float2*)(xb0 + 16384));
    float2 xg = __ldg((const float2*)(xb0 + 32768));
    float2 xo = __ldg((const float2*)(xb0 + 49152));

    for (int step = 0; step < 512; step++) {
        const int t = dir ? (511 - step) : step;
        const float* hsrc = g_hstate[dir][step & 1];

        // prologue: prefetch h chunk 0 into buf0
        {
            const float4* src = (const float4*)hsrc;
            float4* dst = (float4*)sh0;
#pragma unroll
            for (int i = 0; i < 8; i++) cp16(dst + tid + (i << 7), src + tid + (i << 7));
            cp_commit();
        }

        unsigned long long A00 = 0, A01 = 0, A10 = 0, A11 = 0;
#pragma unroll
        for (int ch = 0; ch < 4; ch++) {
            cp_wait<0>();
            __syncthreads();                       // data ready + prev readers done
            if (ch < 3) {
                // write target (ch+1)%3 was last read in chunk ch-2 (done at sync of ch-1)
                const float4* src = (const float4*)hsrc + ((ch + 1) << 10);
                float4* dst = (float4*)((ch + 1) % 3 == 0 ? sh0 : ((ch + 1) % 3 == 1 ? sh1 : sh2));
#pragma unroll
                for (int i = 0; i < 8; i++) cp16(dst + tid + (i << 7), src + tid + (i << 7));
                cp_commit();
            }
            const float* buf = (ch % 3 == 0) ? sh0 : ((ch % 3 == 1) ? sh1 : sh2);
            const float2* hb = (const float2*)buf + bp;
            const ulonglong2* wpc = (const ulonglong2*)sW + ((ch * CH_) << 3) + uu;
#pragma unroll 8
            for (int kk = 0; kk < CH_; kk++) {
                float2 h2 = hb[kk << 4];
                ulonglong2 w = wpc[kk << 3];        // w.x=(i,f), w.y=(g,o)
                unsigned long long hh0 = pk2(h2.x, h2.x);
                unsigned long long hh1 = pk2(h2.y, h2.y);
                fma2(A00, hh0, w.x); fma2(A01, hh0, w.y);
                fma2(A10, hh1, w.x); fma2(A11, hh1, w.y);
            }
        }

        float ai0, af0, ag0, ao0, ai1, af1, ag1, ao1;
        upk2(ai0, af0, A00); upk2(ag0, ao0, A01);
        upk2(ai1, af1, A10); upk2(ag1, ao1, A11);

        float ig0 = sigm(ai0 + xi.x), fg0 = sigm(af0 + xf.x);
        float gg0 = tanhp(ag0 + xg.x), og0 = sigm(ao0 + xo.x);
        c0 = fg0 * c0 + ig0 * gg0;
        float hv0 = og0 * tanhp(c0);
        float ig1 = sigm(ai1 + xi.y), fg1 = sigm(af1 + xf.y);
        float gg1 = tanhp(ag1 + xg.y), og1 = sigm(ao1 + xo.y);
        c1 = fg1 * c1 + ig1 * gg1;
        float hv1 = og1 * tanhp(c1);

        int hidx = (u0 + uu) * 32 + (bp << 1);
        __stcg((float2*)&g_hstate[dir][(step + 1) & 1][hidx], make_float2(hv0, hv1));
        __threadfence();   // release: h visible at L2 before arrive

        // work not needed by peers goes AFTER the fence, hidden under the spin:
        *(float2*)(outbuf + (size_t)t * 32768 +
                   (size_t)((dir << 9) + u0 + uu) * 32 + (bp << 1)) = make_float2(hv0, hv1);
        {
            int sn = (step < 511) ? (step + 1) : step;
            int tn = dir ? (511 - sn) : sn;
            const float* xbn = xw + (size_t)tn * 65536 + (size_t)(u0 + uu) * 32 + (bp << 1);
            xi = __ldg((const float2*)(xbn));
            xf = __ldg((const float2*)(xbn + 16384));
            xg = __ldg((const float2*)(xbn + 32768));
            xo = __ldg((const float2*)(xbn + 49152));
        }

        __syncthreads();                  // all threads fenced before arrive
        if (tid == 0) atomicAdd(bar, 1u);
        target += 64;
        if (tid == 0) {
            while (*((volatile unsigned*)bar) < target) { __nanosleep(32); }
        }
        __syncthreads();
        // no acquire fence: h reads go through cp.async.cg (L2-direct) and are
        // program-ordered after the observed spin exit.
    }
}

// ---------------- classifier + log_softmax, out[b][c][tt] ----------------
__global__ __launch_bounds__(256) void classifier_k(
    const float* __restrict__ h, const float* __restrict__ Wc,
    const float* __restrict__ bc, const float* __restrict__ truth,
    const int* __restrict__ tf, float* __restrict__ out)
{
    __shared__ float sL[32][33];
    const int tt = blockIdx.x, tid = threadIdx.x;
    const int b = tid & 31, cg = tid >> 5;
    float acc0 = 0.f, acc1 = 0.f, acc2 = 0.f, acc3 = 0.f;
    const float* hp = h + (size_t)tt * (1024 * B_) + b;
    const float* w0 = Wc + (size_t)(cg * 4 + 0) * 1025 + 1;
    const float* w1 = Wc + (size_t)(cg * 4 + 1) * 1025 + 1;
    const float* w2 = Wc + (size_t)(cg * 4 + 2) * 1025 + 1;
    const float* w3 = Wc + (size_t)(cg * 4 + 3) * 1025 + 1;
#pragma unroll 4
    for (int k = 0; k < 1024; k++) {
        float hv = __ldg(hp + (size_t)k * 32);
        acc0 += hv * __ldg(w0 + k);
        acc1 += hv * __ldg(w1 + k);
        acc2 += hv * __ldg(w2 + k);
        acc3 += hv * __ldg(w3 + k);
    }
    float past = 0.f;
    if (tf[0] != 0 && tt > 0) past = truth[(size_t)b * T_ + tt - 1];
    {
        float a[4] = {acc0, acc1, acc2, acc3};
#pragma unroll
        for (int j = 0; j < 4; j++) {
            int c = cg * 4 + j;
            sL[b][c] = a[j] + __ldg(bc + c) + past * __ldg(Wc + (size_t)c * 1025);
        }
    }
    __syncthreads();
    int w = tid >> 5, lane = tid & 31;
    for (int rep = 0; rep < 4; rep++) {
        int bb = w + (rep << 3);
        float v = sL[bb][lane];
        float m = v;
#pragma unroll
        for (int o = 16; o > 0; o >>= 1) m = fmaxf(m, __shfl_xor_sync(0xffffffffu, m, o));
        float e = expf(v - m);
        float s = e;
#pragma unroll
        for (int o = 16; o > 0; o >>= 1) s += __shfl_xor_sync(0xffffffffu, s, o);
        out[((size_t)bb * 32 + lane) * T_ + tt] = v - m - logf(s);
    }
}

// ---------------- launch ----------------
extern "C" void kernel_launch(void* const* d_in, const int* in_sizes, int n_in,
                              void* d_out, int out_size)
{
    (void)in_sizes; (void)n_in; (void)out_size;
    const int*   x     = (const int*)d_in[0];
    const float* truth = (const float*)d_in[1];
    const int*   tf    = (const int*)d_in[2];
    const float* emb   = (const float*)d_in[3];
    const float* Wih0f = (const float*)d_in[4];
    const float* Whh0f = (const float*)d_in[5];
    const float* bih0f = (const float*)d_in[6];
    const float* bhh0f = (const float*)d_in[7];
    const float* Wih0b = (const float*)d_in[8];
    const float* Whh0b = (const float*)d_in[9];
    const float* bih0b = (const float*)d_in[10];
    const float* bhh0b = (const float*)d_in[11];
    const float* Wih1f = (const float*)d_in[12];
    const float* Whh1f = (const float*)d_in[13];
    const float* bih1f = (const float*)d_in[14];
    const float* bhh1f = (const float*)d_in[15];
    const float* Wih1b = (const float*)d_in[16];
    const float* Whh1b = (const float*)d_in[17];
    const float* bih1b = (const float*)d_in[18];
    const float* bhh1b = (const float*)d_in[19];
    const float* Wc    = (const float*)d_in[20];
    const float* bc    = (const float*)d_in[21];
    float* out = (float*)d_out;

    void *p_embout, *p_xwf, *p_xwb, *p_l1in, *p_l2out;
    cudaGetSymbolAddress(&p_embout, g_embout);
    cudaGetSymbolAddress(&p_xwf, g_xwf);
    cudaGetSymbolAddress(&p_xwb, g_xwb);
    cudaGetSymbolAddress(&p_l1in, g_l1in);
    cudaGetSymbolAddress(&p_l2out, g_l2out);

    const int scan_smem = (512 * 32 + 3 * CH_ * 32) * 4;   // 65536 + 49152 = 114688 B
    cudaFuncSetAttribute(lstm_scan, cudaFuncAttributeMaxDynamicSharedMemorySize, scan_smem);

    dim3 ggrid(32, 128);  // N/64, M/128

    embed_k<<<T_, 256>>>(x, emb, (float*)p_embout);
    reset_k<<<64, 256>>>();
    gemm_xw<<<ggrid, 256>>>((const float*)p_embout, Wih0f, bih0f, bhh0f, (float*)p_xwf, 512);
    gemm_xw<<<ggrid, 256>>>((const float*)p_embout, Wih0b, bih0b, bhh0b, (float*)p_xwb, 512);
    lstm_scan<<<128, 128, scan_smem>>>((const float*)p_xwf, (const float*)p_xwb,
                                       Whh0f, Whh0b, (float*)p_l1in);
    reset_k<<<64, 256>>>();
    gemm_xw<<<ggrid, 256>>>((const float*)p_l1in, Wih1f, bih1f, bhh1f, (float*)p_xwf, 1024);
    gemm_xw<<<ggrid, 256>>>((const float*)p_l1in, Wih1b, bih1b, bhh1b, (float*)p_xwb, 1024);
    lstm_scan<<<128, 128, scan_smem>>>((const float*)p_xwf, (const float*)p_xwb,
                                       Whh1f, Whh1b, (float*)p_l2out);
    classifier_k<<<T_, 256>>>((const float*)p_l2out, Wc, bc, truth, tf, out);
}